// round 4
// baseline (speedup 1.0000x reference)
#include <cuda_runtime.h>

#define NC 256
#define NH 256
#define NW 256
#define NBOX 100

__global__ __launch_bounds__(256)
void fused_kernel(const float* __restrict__ boxes,
                  const float* __restrict__ scores,
                  const float* __restrict__ feat,
                  float4* __restrict__ out) {
    __shared__ float s_sc[NBOX];
    __shared__ int   s_idx[NBOX];
    __shared__ float s_a[NBOX], s_cx[NBOX], s_cy[NBOX], s_r2[NBOX];
    __shared__ float s_w[NBOX][4];
    __shared__ int   s_o[NBOX][4];
    __shared__ float4 red[256];
    __shared__ float4 s_coef;   // A, B1, B2, D

    const int tid = threadIdx.x;
    const int c   = blockIdx.x;

    // ---- Phase A: stage scores to smem, serial compaction over smem ----
    if (tid < NBOX) s_sc[tid] = scores[tid];
    __syncthreads();
    if (tid == 0) {
        int cnt = 0;
        #pragma unroll 4
        for (int i = 0; i < NBOX; i++)
            if (s_sc[i] > 0.0f) s_idx[cnt++] = i;
        for (int i = cnt; i < NBOX; i++) s_idx[i] = 0;   // nonzero fill_value=0
    }
    __syncthreads();

    // ---- Phase B: per-box params + grid_sample weights/offsets ----
    if (tid < NBOX) {
        const float4* b4 = (const float4*)(boxes + (size_t)s_idx[tid] * 24);
        // 24 floats = 6 float4; corners are (x,y,z) triples
        float4 v0 = b4[0], v1 = b4[1], v2 = b4[2], v3 = b4[3], v4 = b4[4], v5 = b4[5];
        // x coords: indices 0,3,6,9,12,15,18,21 ; y: 1,4,7,10,13,16,19,22
        float xs[8] = {v0.x, v0.w, v1.z, v2.y, v3.x, v3.w, v4.z, v5.y};
        float ys[8] = {v0.y, v1.x, v1.w, v2.z, v3.y, v4.x, v4.w, v5.z};
        float lx = xs[0], rx = xs[0], ly = ys[0], ry = ys[0];
        #pragma unroll
        for (int k = 1; k < 8; k++) {
            lx = fminf(lx, xs[k]); rx = fmaxf(rx, xs[k]);
            ly = fminf(ly, ys[k]); ry = fmaxf(ry, ys[k]);
        }
        float cx  = ((lx + rx) * 0.5f + 128.0f) / 160.0f;
        float cy  = ((ly + ry) * 0.5f + 128.0f) / 160.0f;
        float bev = ((ry - ly) / 160.0f) * ((rx - lx) / 160.0f);
        float a   = 1.0f / (2.0f * bev * bev);
        s_cx[tid] = cx; s_cy[tid] = cy; s_a[tid] = a;
        s_r2[tid] = cx * cx + cy * cy;

        // bilinear grid_sample (zero pad, align_corners=False)
        float ix = ((cx + 1.0f) * (float)NW - 1.0f) * 0.5f;
        float iy = ((cy + 1.0f) * (float)NH - 1.0f) * 0.5f;
        float x0f = floorf(ix), y0f = floorf(iy);
        float wx1 = ix - x0f, wx0 = 1.0f - wx1;
        float wy1 = iy - y0f, wy0 = 1.0f - wy1;
        int x0 = (int)x0f, y0 = (int)y0f, x1 = x0 + 1, y1 = y0 + 1;
        bool vx0 = (x0 >= 0 && x0 < NW), vx1 = (x1 >= 0 && x1 < NW);
        bool vy0 = (y0 >= 0 && y0 < NH), vy1 = (y1 >= 0 && y1 < NH);
        int cx0 = min(max(x0, 0), NW - 1), cx1 = min(max(x1, 0), NW - 1);
        int cy0 = min(max(y0, 0), NH - 1), cy1 = min(max(y1, 0), NH - 1);
        s_w[tid][0] = (vx0 && vy0) ? wx0 * wy0 : 0.0f;  s_o[tid][0] = cy0 * NW + cx0;
        s_w[tid][1] = (vx1 && vy0) ? wx1 * wy0 : 0.0f;  s_o[tid][1] = cy0 * NW + cx1;
        s_w[tid][2] = (vx0 && vy1) ? wx0 * wy1 : 0.0f;  s_o[tid][2] = cy1 * NW + cx0;
        s_w[tid][3] = (vx1 && vy1) ? wx1 * wy1 : 0.0f;  s_o[tid][3] = cy1 * NW + cx1;
    }
    __syncthreads();

    // ---- Phase C: gather feat + reduce to 4 channel coefficients ----
    float4 acc = make_float4(0.f, 0.f, 0.f, 0.f);
    if (tid < NBOX) {
        const float* fc = feat + (size_t)c * NH * NW;
        float v = s_w[tid][0] * __ldg(fc + s_o[tid][0])
                + s_w[tid][1] * __ldg(fc + s_o[tid][1])
                + s_w[tid][2] * __ldg(fc + s_o[tid][2])
                + s_w[tid][3] * __ldg(fc + s_o[tid][3]);
        float ta = v * s_a[tid];
        acc = make_float4(ta, ta * s_cx[tid], ta * s_cy[tid], ta * s_r2[tid]);
    }
    red[tid] = acc;
    __syncthreads();
    #pragma unroll
    for (int s = 128; s > 0; s >>= 1) {
        if (tid < s) {
            float4 u = red[tid], v = red[tid + s];
            red[tid] = make_float4(u.x + v.x, u.y + v.y, u.z + v.z, u.w + v.w);
        }
        __syncthreads();
    }
    if (tid == 0) {
        const float inv = 1.0f / (float)NBOX;
        float4 r = red[0];
        s_coef = make_float4(r.x * inv, 2.0f * r.y * inv, 2.0f * r.z * inv, r.w * inv);
    }
    __syncthreads();

    // ---- Phase D: write out[c,h,w] = w*(w*A - B1) + h*(h*A - B2) + D ----
    const float A  = s_coef.x;
    const float B1 = s_coef.y;
    const float B2 = s_coef.z;
    const float D  = s_coef.w;
    float4* oc = out + (size_t)c * (NH * NW / 4);
    #pragma unroll 4
    for (int i = tid; i < NH * NW / 4; i += 256) {
        float hf   = (float)(i >> 6);
        float base = fmaf(hf, fmaf(hf, A, -B2), D);
        float w0   = (float)((i & 63) * 4);
        float4 r;
        float w;
        w = w0;        r.x = fmaf(w, fmaf(w, A, -B1), base);
        w = w0 + 1.f;  r.y = fmaf(w, fmaf(w, A, -B1), base);
        w = w0 + 2.f;  r.z = fmaf(w, fmaf(w, A, -B1), base);
        w = w0 + 3.f;  r.w = fmaf(w, fmaf(w, A, -B1), base);
        oc[i] = r;
    }
}

extern "C" void kernel_launch(void* const* d_in, const int* in_sizes, int n_in,
                              void* d_out, int out_size) {
    const float* boxes  = (const float*)d_in[0];   // [100,8,3]
    const float* scores = (const float*)d_in[1];   // [100]
    const float* feat   = (const float*)d_in[2];   // [1,256,256,256]
    fused_kernel<<<NC, 256>>>(boxes, scores, feat, (float4*)d_out);
    (void)in_sizes; (void)n_in; (void)out_size;
}

// round 5
// speedup vs baseline: 1.1267x; 1.1267x over previous
#include <cuda_runtime.h>

#define NC 256
#define NH 256
#define NW 256
#define NBOX 100
#define SLICES 8           // blocks per channel
#define ROWS_PER_SLICE (NH / SLICES)   // 32

__global__ __launch_bounds__(256)
void fused_kernel(const float* __restrict__ boxes,
                  const float* __restrict__ scores,
                  const float* __restrict__ feat,
                  float4* __restrict__ out) {
    __shared__ float4 red[256];
    __shared__ int    s_pc[8];
    __shared__ float4 s_coef;   // A, B1, B2, D

    const int tid   = threadIdx.x;
    const int c     = blockIdx.x >> 3;   // channel
    const int slice = blockIdx.x & 7;    // row-slice within channel

    // ---- Phase A: score mask + parallel count (no serial compaction) ----
    int m = 0;
    if (tid < NBOX) m = (scores[tid] > 0.0f) ? 1 : 0;
    unsigned bal = __ballot_sync(0xffffffffu, m);
    if ((tid & 31) == 0) s_pc[tid >> 5] = __popc(bal);
    __syncthreads();
    const int cnt = s_pc[0] + s_pc[1] + s_pc[2] + s_pc[3]
                  + s_pc[4] + s_pc[5] + s_pc[6] + s_pc[7];

    // ---- Phase B+C: per-box params, gather, weighted contribution ----
    // Sum over the reference's 100 slots = each selected box once
    // + (100 - cnt) extra copies of box 0 (nonzero fill_value = 0).
    float4 acc = make_float4(0.f, 0.f, 0.f, 0.f);
    if (tid < NBOX) {
        const float4* b4 = (const float4*)(boxes + (size_t)tid * 24);
        float4 v0 = b4[0], v1 = b4[1], v2 = b4[2], v3 = b4[3], v4 = b4[4], v5 = b4[5];
        // corners are (x,y,z) triples: x at 0,3,..,21 ; y at 1,4,..,22
        float xs[8] = {v0.x, v0.w, v1.z, v2.y, v3.x, v3.w, v4.z, v5.y};
        float ys[8] = {v0.y, v1.x, v1.w, v2.z, v3.y, v4.x, v4.w, v5.z};
        float lx = xs[0], rx = xs[0], ly = ys[0], ry = ys[0];
        #pragma unroll
        for (int k = 1; k < 8; k++) {
            lx = fminf(lx, xs[k]); rx = fmaxf(rx, xs[k]);
            ly = fminf(ly, ys[k]); ry = fmaxf(ry, ys[k]);
        }
        float cx  = ((lx + rx) * 0.5f + 128.0f) / 160.0f;
        float cy  = ((ly + ry) * 0.5f + 128.0f) / 160.0f;
        float bev = ((ry - ly) / 160.0f) * ((rx - lx) / 160.0f);
        float a   = 1.0f / (2.0f * bev * bev);
        float r2  = cx * cx + cy * cy;

        // bilinear grid_sample (zero pad, align_corners=False)
        float ix = ((cx + 1.0f) * (float)NW - 1.0f) * 0.5f;
        float iy = ((cy + 1.0f) * (float)NH - 1.0f) * 0.5f;
        float x0f = floorf(ix), y0f = floorf(iy);
        float wx1 = ix - x0f, wx0 = 1.0f - wx1;
        float wy1 = iy - y0f, wy0 = 1.0f - wy1;
        int x0 = (int)x0f, y0 = (int)y0f, x1 = x0 + 1, y1 = y0 + 1;
        bool vx0 = (x0 >= 0 && x0 < NW), vx1 = (x1 >= 0 && x1 < NW);
        bool vy0 = (y0 >= 0 && y0 < NH), vy1 = (y1 >= 0 && y1 < NH);
        int px0 = min(max(x0, 0), NW - 1), px1 = min(max(x1, 0), NW - 1);
        int py0 = min(max(y0, 0), NH - 1), py1 = min(max(y1, 0), NH - 1);
        float w00 = (vx0 && vy0) ? wx0 * wy0 : 0.0f;
        float w10 = (vx1 && vy0) ? wx1 * wy0 : 0.0f;
        float w01 = (vx0 && vy1) ? wx0 * wy1 : 0.0f;
        float w11 = (vx1 && vy1) ? wx1 * wy1 : 0.0f;

        const float* fc = feat + (size_t)c * NH * NW;
        float v = w00 * __ldg(fc + py0 * NW + px0)
                + w10 * __ldg(fc + py0 * NW + px1)
                + w01 * __ldg(fc + py1 * NW + px0)
                + w11 * __ldg(fc + py1 * NW + px1);

        float mult = (tid == 0) ? (float)(m + NBOX - cnt) : (float)m;
        float ta = v * a * mult;
        acc = make_float4(ta, ta * cx, ta * cy, ta * r2);
    }
    red[tid] = acc;
    __syncthreads();

    // ---- block reduction to 4 coefficients ----
    #pragma unroll
    for (int s = 128; s > 0; s >>= 1) {
        if (tid < s) {
            float4 u = red[tid], v = red[tid + s];
            red[tid] = make_float4(u.x + v.x, u.y + v.y, u.z + v.z, u.w + v.w);
        }
        __syncthreads();
    }
    if (tid == 0) {
        const float inv = 1.0f / (float)NBOX;
        float4 r = red[0];
        s_coef = make_float4(r.x * inv, 2.0f * r.y * inv, 2.0f * r.z * inv, r.w * inv);
    }
    __syncthreads();

    // ---- Phase D: out[c,h,w] = w*(w*A - B1) + h*(h*A - B2) + D ----
    const float A  = s_coef.x;
    const float B1 = s_coef.y;
    const float B2 = s_coef.z;
    const float D  = s_coef.w;
    float4* oc = out + (size_t)c * (NH * NW / 4) + slice * (ROWS_PER_SLICE * NW / 4);
    #pragma unroll
    for (int k = 0; k < (ROWS_PER_SLICE * NW / 4) / 256; k++) {   // 8 iters
        int i = k * 256 + tid;
        float hf   = (float)(slice * ROWS_PER_SLICE + (i >> 6));
        float base = fmaf(hf, fmaf(hf, A, -B2), D);
        float w0   = (float)((i & 63) * 4);
        float4 r;
        float w;
        w = w0;        r.x = fmaf(w, fmaf(w, A, -B1), base);
        w = w0 + 1.f;  r.y = fmaf(w, fmaf(w, A, -B1), base);
        w = w0 + 2.f;  r.z = fmaf(w, fmaf(w, A, -B1), base);
        w = w0 + 3.f;  r.w = fmaf(w, fmaf(w, A, -B1), base);
        oc[i] = r;
    }
}

extern "C" void kernel_launch(void* const* d_in, const int* in_sizes, int n_in,
                              void* d_out, int out_size) {
    const float* boxes  = (const float*)d_in[0];   // [100,8,3]
    const float* scores = (const float*)d_in[1];   // [100]
    const float* feat   = (const float*)d_in[2];   // [1,256,256,256]
    fused_kernel<<<NC * SLICES, 256>>>(boxes, scores, feat, (float4*)d_out);
    (void)in_sizes; (void)n_in; (void)out_size;
}

// round 6
// speedup vs baseline: 1.2315x; 1.0930x over previous
#include <cuda_runtime.h>

#define NC 256
#define NH 256
#define NW 256
#define NBOX 100
#define SLICES 8                       // writer blocks per channel
#define ROWS_PER_SLICE (NH / SLICES)   // 32

__device__ float4 g_coef[NC];          // A, B1, B2, D per channel

// ---------------------------------------------------------------------------
// Kernel 1: per-channel coefficients, one block per channel, fully parallel.
//   S0 = sum_n cpf*a, S1 = sum cpf*a*cx, S2 = sum cpf*a*cy, S3 = sum cpf*a*(cx^2+cy^2)
// nonzero(size=100, fill=0) == each selected box once + (100-cnt) copies of box 0.
// ---------------------------------------------------------------------------
__global__ __launch_bounds__(128)
void coef_kernel(const float* __restrict__ boxes,
                 const float* __restrict__ scores,
                 const float* __restrict__ feat) {
    __shared__ float4 red[128];
    __shared__ int    s_pc[4];
    const int tid = threadIdx.x;
    const int c   = blockIdx.x;

    int m = 0;
    if (tid < NBOX) m = (scores[tid] > 0.0f) ? 1 : 0;
    unsigned bal = __ballot_sync(0xffffffffu, m);
    if ((tid & 31) == 0) s_pc[tid >> 5] = __popc(bal);
    __syncthreads();
    const int cnt = s_pc[0] + s_pc[1] + s_pc[2] + s_pc[3];

    float4 acc = make_float4(0.f, 0.f, 0.f, 0.f);
    if (tid < NBOX) {
        const float4* b4 = (const float4*)(boxes + (size_t)tid * 24);
        float4 v0 = b4[0], v1 = b4[1], v2 = b4[2], v3 = b4[3], v4 = b4[4], v5 = b4[5];
        // corners are (x,y,z) triples: x at 0,3,..,21 ; y at 1,4,..,22
        float xs[8] = {v0.x, v0.w, v1.z, v2.y, v3.x, v3.w, v4.z, v5.y};
        float ys[8] = {v0.y, v1.x, v1.w, v2.z, v3.y, v4.x, v4.w, v5.z};
        float lx = xs[0], rx = xs[0], ly = ys[0], ry = ys[0];
        #pragma unroll
        for (int k = 1; k < 8; k++) {
            lx = fminf(lx, xs[k]); rx = fmaxf(rx, xs[k]);
            ly = fminf(ly, ys[k]); ry = fmaxf(ry, ys[k]);
        }
        float cx  = ((lx + rx) * 0.5f + 128.0f) / 160.0f;
        float cy  = ((ly + ry) * 0.5f + 128.0f) / 160.0f;
        float bev = ((ry - ly) / 160.0f) * ((rx - lx) / 160.0f);
        float a   = 1.0f / (2.0f * bev * bev);
        float r2  = cx * cx + cy * cy;

        // bilinear grid_sample (zero pad, align_corners=False)
        float ix = ((cx + 1.0f) * (float)NW - 1.0f) * 0.5f;
        float iy = ((cy + 1.0f) * (float)NH - 1.0f) * 0.5f;
        float x0f = floorf(ix), y0f = floorf(iy);
        float wx1 = ix - x0f, wx0 = 1.0f - wx1;
        float wy1 = iy - y0f, wy0 = 1.0f - wy1;
        int x0 = (int)x0f, y0 = (int)y0f, x1 = x0 + 1, y1 = y0 + 1;
        bool vx0 = (x0 >= 0 && x0 < NW), vx1 = (x1 >= 0 && x1 < NW);
        bool vy0 = (y0 >= 0 && y0 < NH), vy1 = (y1 >= 0 && y1 < NH);
        int px0 = min(max(x0, 0), NW - 1), px1 = min(max(x1, 0), NW - 1);
        int py0 = min(max(y0, 0), NH - 1), py1 = min(max(y1, 0), NH - 1);
        float w00 = (vx0 && vy0) ? wx0 * wy0 : 0.0f;
        float w10 = (vx1 && vy0) ? wx1 * wy0 : 0.0f;
        float w01 = (vx0 && vy1) ? wx0 * wy1 : 0.0f;
        float w11 = (vx1 && vy1) ? wx1 * wy1 : 0.0f;

        const float* fc = feat + (size_t)c * NH * NW;
        float v = w00 * __ldg(fc + py0 * NW + px0)
                + w10 * __ldg(fc + py0 * NW + px1)
                + w01 * __ldg(fc + py1 * NW + px0)
                + w11 * __ldg(fc + py1 * NW + px1);

        float mult = (tid == 0) ? (float)(m + NBOX - cnt) : (float)m;
        float ta = v * a * mult;
        acc = make_float4(ta, ta * cx, ta * cy, ta * r2);
    }
    red[tid] = acc;
    __syncthreads();
    #pragma unroll
    for (int s = 64; s > 0; s >>= 1) {
        if (tid < s) {
            float4 u = red[tid], v = red[tid + s];
            red[tid] = make_float4(u.x + v.x, u.y + v.y, u.z + v.z, u.w + v.w);
        }
        __syncthreads();
    }
    if (tid == 0) {
        const float inv = 1.0f / (float)NBOX;
        float4 r = red[0];
        g_coef[c] = make_float4(r.x * inv, 2.0f * r.y * inv, 2.0f * r.z * inv, r.w * inv);
    }
}

// ---------------------------------------------------------------------------
// Kernel 2: pure streaming writer. One LDG.128 prologue, then 8 STG.128/thread.
//   out[c,h,w] = w*(w*A - B1) + h*(h*A - B2) + D
// ---------------------------------------------------------------------------
__global__ __launch_bounds__(256)
void out_kernel(float4* __restrict__ out) {
    const int tid   = threadIdx.x;
    const int c     = blockIdx.x >> 3;
    const int slice = blockIdx.x & 7;

    const float4 k4 = __ldg(&g_coef[c]);
    const float A = k4.x, B1 = k4.y, B2 = k4.z, D = k4.w;

    float4* oc = out + (size_t)c * (NH * NW / 4) + slice * (ROWS_PER_SLICE * NW / 4);
    const float w0 = (float)((tid & 63) * 4);
    // w-polynomial is invariant across the 8 rows this thread touches
    const float pw0 = fmaf(w0,        fmaf(w0,        A, -B1), 0.f);
    const float pw1 = fmaf(w0 + 1.f,  fmaf(w0 + 1.f,  A, -B1), 0.f);
    const float pw2 = fmaf(w0 + 2.f,  fmaf(w0 + 2.f,  A, -B1), 0.f);
    const float pw3 = fmaf(w0 + 3.f,  fmaf(w0 + 3.f,  A, -B1), 0.f);

    #pragma unroll
    for (int k = 0; k < 8; k++) {
        int   i    = k * 256 + tid;
        float hf   = (float)(slice * ROWS_PER_SLICE + (i >> 6));
        float base = fmaf(hf, fmaf(hf, A, -B2), D);
        float4 r = make_float4(pw0 + base, pw1 + base, pw2 + base, pw3 + base);
        oc[i] = r;
    }
}

// ---------------------------------------------------------------------------
extern "C" void kernel_launch(void* const* d_in, const int* in_sizes, int n_in,
                              void* d_out, int out_size) {
    const float* boxes  = (const float*)d_in[0];   // [100,8,3]
    const float* scores = (const float*)d_in[1];   // [100]
    const float* feat   = (const float*)d_in[2];   // [1,256,256,256]

    coef_kernel<<<NC, 128>>>(boxes, scores, feat);
    out_kernel<<<NC * SLICES, 256>>>((float4*)d_out);
    (void)in_sizes; (void)n_in; (void)out_size;
}